// round 13
// baseline (speedup 1.0000x reference)
#include <cuda_runtime.h>
#include <cstdint>

#define OH 7
#define OW 7
#define NW 8            // warps per block
#define CH 8            // channels per warp

__device__ __forceinline__ void pick2(const float4& q, float e, int sel,
                                      float& v0, float& v1) {
    // v0 = q[sel], v1 = q[sel+1] (e when sel==3)
    v0 = (sel == 0) ? q.x : (sel == 1) ? q.y : (sel == 2) ? q.z : q.w;
    v1 = (sel == 0) ? q.y : (sel == 1) ? q.z : (sel == 2) ? q.w : e;
}

__global__ void __launch_bounds__(256) roialign_kernel(
        const float* __restrict__ feat,
        const int* __restrict__ rois,
        float* __restrict__ out,
        int C, int H, int W) {
    const int n    = blockIdx.x;
    const int cg   = blockIdx.y;
    const int tid  = threadIdx.x;
    const int warp = tid >> 5, lane = tid & 31;
    const int cbase = (cg * NW + warp) * CH;

    const int* r = rois + n * 5;
    const int b  = __ldg(r);
    const int x1 = __ldg(r + 1), y1 = __ldg(r + 2);
    const int x2 = __ldg(r + 3), y2 = __ldg(r + 4);

    const float dy6 = (float)(y2 - y1) * 0.16666667f;
    const float dx6 = (float)(x2 - x1) * 0.16666667f;
    const float y1f = (float)y1, x1f = (float)x1;

    // ---- per-lane constants: lane = (oy, ox) on an 8x8 padded grid ----
    const int ox  = lane & 7;                 // 0..7 (7 = inactive pad)
    const int oyA = lane >> 3;                // 0..3
    const int oyB = oyA + 4;                  // 4..7 (7 = inactive pad)

    float sx  = x1f + (float)ox * dx6;
    float x0f = floorf(sx);
    const float wx  = sx - x0f;
    const float omx = 1.0f - wx;
    const int ix0 = min(max((int)x0f, 0), W - 1);
    const int ix1 = min(ix0 + 1, W - 1);
    const int sel = ix0 & 3;
    const int xq  = ix0 >> 2;                 // float4 index within row
    const bool needE = (sel == 3);

    float syA = y1f + (float)oyA * dy6;
    float syB = y1f + (float)oyB * dy6;
    float yA0f = floorf(syA), yB0f = floorf(syB);
    const float wyA = syA - yA0f, wyB = syB - yB0f;
    const float omyA = 1.0f - wyA, omyB = 1.0f - wyB;
    const int iyA0 = min(max((int)yA0f, 0), H - 1);
    const int iyA1 = min(iyA0 + 1, H - 1);
    const int iyB0 = min(max((int)yB0f, 0), H - 1);
    const int iyB1 = min(iyB0 + 1, H - 1);

    // float4-index offsets (row offsets iy*W are divisible by 4 since W%4==0)
    const int W4 = W >> 2;
    const int fA0 = iyA0 * W4 + xq, fA1 = iyA1 * W4 + xq;
    const int fB0 = iyB0 * W4 + xq, fB1 = iyB1 * W4 + xq;
    // scalar offsets for the rare 4th-element neighbor (sel==3)
    const int eA0 = iyA0 * W + ix1, eA1 = iyA1 * W + ix1;
    const int eB0 = iyB0 * W + ix1, eB1 = iyB1 * W + ix1;

    const size_t HW = (size_t)(H * W);
    const float* g  = feat + ((size_t)b * C + cbase) * HW;
    float* obase    = out + ((size_t)(n * C + cbase)) * (OH * OW);

    const bool actA = (ox < OW);
    const bool actB = (ox < OW) && (oyB < OH);

    #pragma unroll
    for (int k = 0; k < CH; k++) {
        const float*  gk  = g + (size_t)k * HW;
        const float4* gk4 = (const float4*)gk;

        const float4 qA0 = __ldg(gk4 + fA0);
        const float4 qA1 = __ldg(gk4 + fA1);
        const float4 qB0 = __ldg(gk4 + fB0);
        const float4 qB1 = __ldg(gk4 + fB1);

        float xA0 = 0.f, xA1 = 0.f, xB0 = 0.f, xB1 = 0.f;
        if (needE) {
            xA0 = __ldg(gk + eA0);
            xA1 = __ldg(gk + eA1);
            xB0 = __ldg(gk + eB0);
            xB1 = __ldg(gk + eB1);
        }

        float a00, a01, a10, a11, b00, b01, b10, b11;
        pick2(qA0, xA0, sel, a00, a01);
        pick2(qA1, xA1, sel, a10, a11);
        pick2(qB0, xB0, sel, b00, b01);
        pick2(qB1, xB1, sel, b10, b11);

        float* o = obase + k * (OH * OW);
        if (actA)
            o[oyA * OW + ox] = (a00 * omx + a01 * wx) * omyA
                             + (a10 * omx + a11 * wx) * wyA;
        if (actB)
            o[oyB * OW + ox] = (b00 * omx + b01 * wx) * omyB
                             + (b10 * omx + b11 * wx) * wyB;
    }
}

extern "C" void kernel_launch(void* const* d_in, const int* in_sizes, int n_in,
                              void* d_out, int out_size) {
    const float* feat = (const float*)d_in[0];
    const int*   rois = (const int*)d_in[1];
    float*       out  = (float*)d_out;

    const int C = 256, H = 200, W = 200;
    const int N = in_sizes[1] / 5;

    dim3 grid(N, C / (NW * CH));
    roialign_kernel<<<grid, NW * 32>>>(feat, rois, out, C, H, W);
}

// round 14
// speedup vs baseline: 1.0814x; 1.0814x over previous
#include <cuda_runtime.h>
#include <cstdint>

#define OH 7
#define OW 7
#define NW 8            // warps per block
#define CH 8            // channels per warp

__global__ void __launch_bounds__(256) roialign_kernel(
        const float* __restrict__ feat,
        const int* __restrict__ rois,
        float* __restrict__ out,
        int C, int H, int W) {
    const int n    = blockIdx.x;
    const int cg   = blockIdx.y;
    const int tid  = threadIdx.x;
    const int warp = tid >> 5, lane = tid & 31;
    const int cbase = (cg * NW + warp) * CH;

    const int* r = rois + n * 5;
    const int b  = __ldg(r);
    const int x1 = __ldg(r + 1), y1 = __ldg(r + 2);
    const int x2 = __ldg(r + 3), y2 = __ldg(r + 4);

    const float dy6 = (float)(y2 - y1) * 0.16666667f;
    const float dx6 = (float)(x2 - x1) * 0.16666667f;
    const float y1f = (float)y1, x1f = (float)x1;

    // ---- lane decomposition: (rowsel, corner, ox) = 2 x 2 x 8 ----
    const int ox     = lane & 7;        // 0..7 (7 = pad, never written)
    const int corner = (lane >> 3) & 1; // 0: x0, 1: x1
    const int rowsel = lane >> 4;       // 0: y0-row, 1: y1-row

    // per-lane x corner + weight factor
    float sx  = x1f + (float)ox * dx6;
    float x0f = floorf(sx);
    const float wx  = sx - x0f;
    const int ix0 = min(max((int)x0f, 0), W - 1);
    const int ix  = corner ? min(ix0 + 1, W - 1) : ix0;
    const float wxc = corner ? wx : (1.0f - wx);

    // per-lane offsets + combined weights for all 7 output rows
    int   off[OH];
    float wt[OH];
    #pragma unroll
    for (int oy = 0; oy < OH; oy++) {
        float sy  = y1f + (float)oy * dy6;
        float y0f = floorf(sy);
        const float wy = sy - y0f;
        int iy0 = min(max((int)y0f, 0), H - 1);
        int iy1 = min(iy0 + 1, H - 1);
        const int row   = rowsel ? iy1 : iy0;
        const float wyc = rowsel ? wy : (1.0f - wy);
        off[oy] = row * W + ix;
        wt[oy]  = wxc * wyc;
    }

    const size_t HW = (size_t)(H * W);
    const float* g  = feat + ((size_t)b * C + cbase) * HW;
    float* obase    = out + ((size_t)(n * C + cbase)) * (OH * OW);

    const bool wr = (lane < OW);        // lanes 0..6 (corner=0,rowsel=0) write

    #pragma unroll
    for (int k = 0; k < CH; k++) {
        const float* gk = g + (size_t)k * HW;
        float* o = obase + k * (OH * OW);

        // load all 7 corner values first (independent -> full MLP)
        float v[OH];
        #pragma unroll
        for (int oy = 0; oy < OH; oy++)
            v[oy] = __ldg(gk + off[oy]) * wt[oy];

        // butterfly-reduce the 4 (corner,rowsel) partials per (oy, ox)
        #pragma unroll
        for (int oy = 0; oy < OH; oy++) {
            float s = v[oy];
            s += __shfl_xor_sync(0xffffffffu, s, 8);
            s += __shfl_xor_sync(0xffffffffu, s, 16);
            if (wr) o[oy * OW + ox] = s;
        }
    }
}

extern "C" void kernel_launch(void* const* d_in, const int* in_sizes, int n_in,
                              void* d_out, int out_size) {
    const float* feat = (const float*)d_in[0];
    const int*   rois = (const int*)d_in[1];
    float*       out  = (float*)d_out;

    const int C = 256, H = 200, W = 200;
    const int N = in_sizes[1] / 5;

    dim3 grid(N, C / (NW * CH));
    roialign_kernel<<<grid, NW * 32>>>(feat, rois, out, C, H, W);
}

// round 15
// speedup vs baseline: 1.2763x; 1.1803x over previous
#include <cuda_runtime.h>
#include <cstdint>

#define OH 7
#define OW 7
#define NW 4            // warps per block (small blocks -> smoother tail)
#define CH 8            // channels per warp

__global__ void __launch_bounds__(128) roialign_kernel(
        const float* __restrict__ feat,
        const int* __restrict__ rois,
        float* __restrict__ out,
        int C, int H, int W) {
    const int n    = blockIdx.x;
    const int cg   = blockIdx.y;
    const int tid  = threadIdx.x;
    const int warp = tid >> 5, lane = tid & 31;
    const int cbase = (cg * NW + warp) * CH;

    const int* r = rois + n * 5;
    const int b  = __ldg(r);
    const int x1 = __ldg(r + 1), y1 = __ldg(r + 2);
    const int x2 = __ldg(r + 3), y2 = __ldg(r + 4);

    const float dy6 = (float)(y2 - y1) * 0.16666667f;
    const float dx6 = (float)(x2 - x1) * 0.16666667f;
    const float y1f = (float)y1, x1f = (float)x1;

    // ---- per-lane constants: lane = (oy, ox) on an 8x8 padded grid ----
    const int ox  = lane & 7;                 // 0..7 (7 = inactive pad)
    const int oyA = lane >> 3;                // 0..3
    const int oyB = oyA + 4;                  // 4..7 (7 = inactive pad)

    float sx  = x1f + (float)ox * dx6;
    float x0f = floorf(sx);
    const float wx  = sx - x0f;
    const float omx = 1.0f - wx;
    const int ix0 = min(max((int)x0f, 0), W - 1);
    const int ix1 = min(ix0 + 1, W - 1);

    float syA = y1f + (float)oyA * dy6;
    float syB = y1f + (float)oyB * dy6;
    float yA0f = floorf(syA), yB0f = floorf(syB);
    const float wyA = syA - yA0f, wyB = syB - yB0f;
    const float omyA = 1.0f - wyA, omyB = 1.0f - wyB;
    const int iyA0 = min(max((int)yA0f, 0), H - 1);
    const int iyA1 = min(iyA0 + 1, H - 1);
    const int iyB0 = min(max((int)yB0f, 0), H - 1);
    const int iyB1 = min(iyB0 + 1, H - 1);

    // 8 fixed per-lane gather offsets
    const int oA00 = iyA0 * W + ix0, oA01 = iyA0 * W + ix1;
    const int oA10 = iyA1 * W + ix0, oA11 = iyA1 * W + ix1;
    const int oB00 = iyB0 * W + ix0, oB01 = iyB0 * W + ix1;
    const int oB10 = iyB1 * W + ix0, oB11 = iyB1 * W + ix1;

    const size_t HW = (size_t)(H * W);
    const float* g  = feat + ((size_t)b * C + cbase) * HW;
    float* obase    = out + ((size_t)(n * C + cbase)) * (OH * OW);

    const bool actA = (ox < OW);
    const bool actB = (ox < OW) && (oyB < OH);

    #pragma unroll
    for (int k = 0; k < CH; k++) {
        const float* gk = g + (size_t)k * HW;

        // loads predicated on activity: pad lanes generate no wavefronts
        float a00 = 0.f, a01 = 0.f, a10 = 0.f, a11 = 0.f;
        float b00 = 0.f, b01 = 0.f, b10 = 0.f, b11 = 0.f;
        if (actA) {
            a00 = __ldg(gk + oA00);
            a01 = __ldg(gk + oA01);
            a10 = __ldg(gk + oA10);
            a11 = __ldg(gk + oA11);
        }
        if (actB) {
            b00 = __ldg(gk + oB00);
            b01 = __ldg(gk + oB01);
            b10 = __ldg(gk + oB10);
            b11 = __ldg(gk + oB11);
        }

        float* o = obase + k * (OH * OW);
        if (actA)
            o[oyA * OW + ox] = (a00 * omx + a01 * wx) * omyA
                             + (a10 * omx + a11 * wx) * wyA;
        if (actB)
            o[oyB * OW + ox] = (b00 * omx + b01 * wx) * omyB
                             + (b10 * omx + b11 * wx) * wyB;
    }
}

extern "C" void kernel_launch(void* const* d_in, const int* in_sizes, int n_in,
                              void* d_out, int out_size) {
    const float* feat = (const float*)d_in[0];
    const int*   rois = (const int*)d_in[1];
    float*       out  = (float*)d_out;

    const int C = 256, H = 200, W = 200;
    const int N = in_sizes[1] / 5;

    dim3 grid(N, C / (NW * CH));
    roialign_kernel<<<grid, NW * 32>>>(feat, rois, out, C, H, W);
}

// round 16
// speedup vs baseline: 1.3445x; 1.0534x over previous
#include <cuda_runtime.h>
#include <cstdint>

#define OH 7
#define OW 7
#define NW 4            // warps per block
#define CH 4            // channels per warp

__global__ void __launch_bounds__(128) roialign_kernel(
        const float* __restrict__ feat,
        const int* __restrict__ rois,
        float* __restrict__ out,
        int C, int H, int W) {
    const int n    = blockIdx.x;
    const int cg   = blockIdx.y;
    const int tid  = threadIdx.x;
    const int warp = tid >> 5, lane = tid & 31;
    const int cbase = (cg * NW + warp) * CH;

    const int* r = rois + n * 5;
    const int b  = __ldg(r);
    const int x1 = __ldg(r + 1), y1 = __ldg(r + 2);
    const int x2 = __ldg(r + 3), y2 = __ldg(r + 4);

    const float dy6 = (float)(y2 - y1) * 0.16666667f;
    const float dx6 = (float)(x2 - x1) * 0.16666667f;
    const float y1f = (float)y1, x1f = (float)x1;

    // ---- per-lane constants: lane = (oy, ox) on an 8x8 padded grid ----
    const int ox  = lane & 7;                 // 0..7 (7 = inactive pad)
    const int oyA = lane >> 3;                // 0..3
    const int oyB = oyA + 4;                  // 4..7 (7 = inactive pad)

    float sx  = x1f + (float)ox * dx6;
    float x0f = floorf(sx);
    const float wx  = sx - x0f;
    const float omx = 1.0f - wx;
    const int ix0 = min(max((int)x0f, 0), W - 1);
    const int ix1 = min(ix0 + 1, W - 1);

    float syA = y1f + (float)oyA * dy6;
    float syB = y1f + (float)oyB * dy6;
    float yA0f = floorf(syA), yB0f = floorf(syB);
    const float wyA = syA - yA0f, wyB = syB - yB0f;
    const float omyA = 1.0f - wyA, omyB = 1.0f - wyB;
    const int iyA0 = min(max((int)yA0f, 0), H - 1);
    const int iyA1 = min(iyA0 + 1, H - 1);
    const int iyB0 = min(max((int)yB0f, 0), H - 1);
    const int iyB1 = min(iyB0 + 1, H - 1);

    // 8 fixed per-lane gather offsets
    const int oA00 = iyA0 * W + ix0, oA01 = iyA0 * W + ix1;
    const int oA10 = iyA1 * W + ix0, oA11 = iyA1 * W + ix1;
    const int oB00 = iyB0 * W + ix0, oB01 = iyB0 * W + ix1;
    const int oB10 = iyB1 * W + ix0, oB11 = iyB1 * W + ix1;

    const size_t HW = (size_t)(H * W);
    const float* g  = feat + ((size_t)b * C + cbase) * HW;
    float* obase    = out + ((size_t)(n * C + cbase)) * (OH * OW);

    const bool actA = (ox < OW);
    const bool actB = (ox < OW) && (oyB < OH);

    #pragma unroll
    for (int k = 0; k < CH; k++) {
        const float* gk = g + (size_t)k * HW;

        // loads predicated on activity: pad lanes generate no wavefronts
        float a00 = 0.f, a01 = 0.f, a10 = 0.f, a11 = 0.f;
        float b00 = 0.f, b01 = 0.f, b10 = 0.f, b11 = 0.f;
        if (actA) {
            a00 = __ldg(gk + oA00);
            a01 = __ldg(gk + oA01);
            a10 = __ldg(gk + oA10);
            a11 = __ldg(gk + oA11);
        }
        if (actB) {
            b00 = __ldg(gk + oB00);
            b01 = __ldg(gk + oB01);
            b10 = __ldg(gk + oB10);
            b11 = __ldg(gk + oB11);
        }

        float* o = obase + k * (OH * OW);
        if (actA)
            o[oyA * OW + ox] = (a00 * omx + a01 * wx) * omyA
                             + (a10 * omx + a11 * wx) * wyA;
        if (actB)
            o[oyB * OW + ox] = (b00 * omx + b01 * wx) * omyB
                             + (b10 * omx + b11 * wx) * wyB;
    }
}

extern "C" void kernel_launch(void* const* d_in, const int* in_sizes, int n_in,
                              void* d_out, int out_size) {
    const float* feat = (const float*)d_in[0];
    const int*   rois = (const int*)d_in[1];
    float*       out  = (float*)d_out;

    const int C = 256, H = 200, W = 200;
    const int N = in_sizes[1] / 5;

    dim3 grid(N, C / (NW * CH));
    roialign_kernel<<<grid, NW * 32>>>(feat, rois, out, C, H, W);
}

// round 17
// speedup vs baseline: 1.3457x; 1.0010x over previous
#include <cuda_runtime.h>
#include <cstdint>

#define OH 7
#define OW 7
#define NW 4            // warps per block
#define CH 2            // channels per warp

__global__ void __launch_bounds__(128) roialign_kernel(
        const float* __restrict__ feat,
        const int* __restrict__ rois,
        float* __restrict__ out,
        int C, int H, int W) {
    const int n    = blockIdx.x;
    const int cg   = blockIdx.y;
    const int tid  = threadIdx.x;
    const int warp = tid >> 5, lane = tid & 31;
    const int cbase = (cg * NW + warp) * CH;

    const int* r = rois + n * 5;
    const int b  = __ldg(r);
    const int x1 = __ldg(r + 1), y1 = __ldg(r + 2);
    const int x2 = __ldg(r + 3), y2 = __ldg(r + 4);

    const float dy6 = (float)(y2 - y1) * 0.16666667f;
    const float dx6 = (float)(x2 - x1) * 0.16666667f;
    const float y1f = (float)y1, x1f = (float)x1;

    // ---- per-lane constants: lane = (oy, ox) on an 8x8 padded grid ----
    const int ox  = lane & 7;                 // 0..7 (7 = inactive pad)
    const int oyA = lane >> 3;                // 0..3
    const int oyB = oyA + 4;                  // 4..7 (7 = inactive pad)

    float sx  = x1f + (float)ox * dx6;
    float x0f = floorf(sx);
    const float wx  = sx - x0f;
    const float omx = 1.0f - wx;
    const int ix0 = min(max((int)x0f, 0), W - 1);
    const int ix1 = min(ix0 + 1, W - 1);

    float syA = y1f + (float)oyA * dy6;
    float syB = y1f + (float)oyB * dy6;
    float yA0f = floorf(syA), yB0f = floorf(syB);
    const float wyA = syA - yA0f, wyB = syB - yB0f;
    const float omyA = 1.0f - wyA, omyB = 1.0f - wyB;
    const int iyA0 = min(max((int)yA0f, 0), H - 1);
    const int iyA1 = min(iyA0 + 1, H - 1);
    const int iyB0 = min(max((int)yB0f, 0), H - 1);
    const int iyB1 = min(iyB0 + 1, H - 1);

    // 8 fixed per-lane gather offsets
    const int oA00 = iyA0 * W + ix0, oA01 = iyA0 * W + ix1;
    const int oA10 = iyA1 * W + ix0, oA11 = iyA1 * W + ix1;
    const int oB00 = iyB0 * W + ix0, oB01 = iyB0 * W + ix1;
    const int oB10 = iyB1 * W + ix0, oB11 = iyB1 * W + ix1;

    const size_t HW = (size_t)(H * W);
    const float* g  = feat + ((size_t)b * C + cbase) * HW;
    float* obase    = out + ((size_t)(n * C + cbase)) * (OH * OW);

    const bool actA = (ox < OW);
    const bool actB = (ox < OW) && (oyB < OH);

    #pragma unroll
    for (int k = 0; k < CH; k++) {
        const float* gk = g + (size_t)k * HW;

        // loads predicated on activity: pad lanes generate no wavefronts
        float a00 = 0.f, a01 = 0.f, a10 = 0.f, a11 = 0.f;
        float b00 = 0.f, b01 = 0.f, b10 = 0.f, b11 = 0.f;
        if (actA) {
            a00 = __ldg(gk + oA00);
            a01 = __ldg(gk + oA01);
            a10 = __ldg(gk + oA10);
            a11 = __ldg(gk + oA11);
        }
        if (actB) {
            b00 = __ldg(gk + oB00);
            b01 = __ldg(gk + oB01);
            b10 = __ldg(gk + oB10);
            b11 = __ldg(gk + oB11);
        }

        float* o = obase + k * (OH * OW);
        if (actA)
            o[oyA * OW + ox] = (a00 * omx + a01 * wx) * omyA
                             + (a10 * omx + a11 * wx) * wyA;
        if (actB)
            o[oyB * OW + ox] = (b00 * omx + b01 * wx) * omyB
                             + (b10 * omx + b11 * wx) * wyB;
    }
}

extern "C" void kernel_launch(void* const* d_in, const int* in_sizes, int n_in,
                              void* d_out, int out_size) {
    const float* feat = (const float*)d_in[0];
    const int*   rois = (const int*)d_in[1];
    float*       out  = (float*)d_out;

    const int C = 256, H = 200, W = 200;
    const int N = in_sizes[1] / 5;

    dim3 grid(N, C / (NW * CH));
    roialign_kernel<<<grid, NW * 32>>>(feat, rois, out, C, H, W);
}